// round 10
// baseline (speedup 1.0000x reference)
#include <cuda_runtime.h>

#define NB 512
#define TT 1024
#define CC 64

typedef unsigned int u32;

__device__ __forceinline__ u32 pkbf2(float lo, float hi) {
    // d[31:16] = bf16(hi), d[15:0] = bf16(lo)
    u32 r; asm("cvt.rn.bf16x2.f32 %0, %1, %2;" : "=r"(r) : "f"(hi), "f"(lo)); return r;
}
__device__ __forceinline__ float frcp(float x) {
    float r; asm("rcp.approx.f32 %0, %1;" : "=f"(r) : "f"(x)); return r;
}
__device__ __forceinline__ void mma16816(float& c0, float& c1, float& c2, float& c3,
                                         u32 a0, u32 a1, u32 a2, u32 a3,
                                         u32 b0, u32 b1) {
    asm("mma.sync.aligned.m16n8k16.row.col.f32.bf16.bf16.f32 "
        "{%0,%1,%2,%3}, {%4,%5,%6,%7}, {%8,%9}, {%0,%1,%2,%3};"
        : "+f"(c0), "+f"(c1), "+f"(c2), "+f"(c3)
        : "r"(a0), "r"(a1), "r"(a2), "r"(a3), "r"(b0), "r"(b1));
}

__global__ void __launch_bounds__(128, 1) crf_fwd_kernel(
    const float* __restrict__ logits,   // [NB, TT, CC]
    const float* __restrict__ trans,    // [CC, CC]  trans[i][j] = score j->i
    const float* __restrict__ init,     // [CC]
    const int*   __restrict__ lengths,  // [NB]
    const int*   __restrict__ tags,     // [NB, TT]
    float*       __restrict__ out)      // [NB]
{
    const int wid  = threadIdx.x >> 5;
    const int lane = threadIdx.x & 31;
    const int g    = blockIdx.x * 4 + wid;          // grid=128 -> g in [0,512)

    const float* lg = logits + (size_t)g * TT * CC;
    const int len = lengths[g];                     // in [2, 1024], uniform per warp

    const int gid = lane >> 2;                      // 0..7
    const int tig = lane & 3;                       // 0..3
    const int r1  = gid + 16 * tig;                 // this lane's owned states
    const int r2  = r1 + 8;                         // (lane 0 -> rows 0, 8)

    // ---- preload E = exp(trans) as bf16 A-fragments: EA[mt][kt][4]
    u32 EA[4][4][4];
    #pragma unroll
    for (int mt = 0; mt < 4; ++mt) {
        const int row = 16 * mt + gid;
        #pragma unroll
        for (int kt = 0; kt < 4; ++kt) {
            const int col = 16 * kt + 2 * tig;
            const float e00 = __expf(__ldg(trans + row * CC + col));
            const float e01 = __expf(__ldg(trans + row * CC + col + 1));
            const float e10 = __expf(__ldg(trans + (row + 8) * CC + col));
            const float e11 = __expf(__ldg(trans + (row + 8) * CC + col + 1));
            const float e08 = __expf(__ldg(trans + row * CC + col + 8));
            const float e09 = __expf(__ldg(trans + row * CC + col + 9));
            const float e18 = __expf(__ldg(trans + (row + 8) * CC + col + 8));
            const float e19 = __expf(__ldg(trans + (row + 8) * CC + col + 9));
            EA[mt][kt][0] = pkbf2(e00, e01);   // rows gid,   cols 2tig..+1
            EA[mt][kt][1] = pkbf2(e10, e11);   // rows gid+8, cols 2tig..+1
            EA[mt][kt][2] = pkbf2(e08, e09);   // rows gid,   cols 2tig+8..+9
            EA[mt][kt][3] = pkbf2(e18, e19);   // rows gid+8, cols 2tig+8..+9
        }
    }

    // ---- w_0 = exp(init + logits[0]); lives in registers only
    float w1 = __expf(__ldg(init + r1) + __ldg(lg + r1));
    float w2 = __expf(__ldg(init + r2) + __ldg(lg + r2));

    // ---- logit pipeline: F for t=1; raw logits for t+1, t+2 (distance-3 LDG cover)
    float F1 = __expf(__ldg(lg + CC + r1));
    float F2 = __expf(__ldg(lg + CC + r2));
    const int c2i = (2 < len) ? 2 : (len - 1);
    const int c3i = (3 < len) ? 3 : (len - 1);
    float L1A = __ldg(lg + c2i * CC + r1), L1B = __ldg(lg + c2i * CC + r2);
    float L2A = __ldg(lg + c3i * CC + r1), L2B = __ldg(lg + c3i * CC + r2);

    float rn = 1.0f;      // normalizer applied this step (lag-1)
    float lnApp = 0.0f;   // -ln(rn)
    float cacc = 0.0f;    // running log-shift

    const u32 FULL = 0xffffffffu;
    const int s0 = 8 * tig;        // shfl source base: lane 8*tig + kt
    const int s4 = 8 * tig + 4;    // and 8*tig + 4 + kt

    for (int t = 1; t < len; ++t) {
        // LDG for logits[t+3] first — ~2 steps of latency cover
        const int tn = (t + 3 < len) ? (t + 3) : (len - 1);
        const float LnA = __ldg(lg + tn * CC + r1);
        const float LnB = __ldg(lg + tn * CC + r2);
        // F for t+1 (MUFU off the critical chain)
        const float FnA = __expf(L1A);
        const float FnB = __expf(L1B);

        // ---- B fragments straight from registers: no smem, no sync.
        // b0[kt] = {w[16kt+2tig], w[16kt+2tig+1]}  (from w1 of lanes 8tig+kt, 8tig+4+kt)
        // b1[kt] = {w[16kt+2tig+8], w[16kt+2tig+9]} (from w2 of the same lanes)
        u32 b0[4], b1[4];
        #pragma unroll
        for (int kt = 0; kt < 4; ++kt) {
            const float lo0 = __shfl_sync(FULL, w1, s0 + kt);
            const float hi0 = __shfl_sync(FULL, w1, s4 + kt);
            const float lo1 = __shfl_sync(FULL, w2, s0 + kt);
            const float hi1 = __shfl_sync(FULL, w2, s4 + kt);
            b0[kt] = pkbf2(lo0, hi0);
            b1[kt] = pkbf2(lo1, hi1);
        }

        // ---- D = E * w via 16 HMMA; depth-2 accumulation (8 independent chains)
        float ca[4][4], cb[4][4];
        #pragma unroll
        for (int mt = 0; mt < 4; ++mt)
            #pragma unroll
            for (int i = 0; i < 4; ++i) { ca[mt][i] = 0.0f; cb[mt][i] = 0.0f; }
        #pragma unroll
        for (int mt = 0; mt < 4; ++mt)
            mma16816(ca[mt][0], ca[mt][1], ca[mt][2], ca[mt][3],
                     EA[mt][0][0], EA[mt][0][1], EA[mt][0][2], EA[mt][0][3],
                     b0[0], b1[0]);
        #pragma unroll
        for (int mt = 0; mt < 4; ++mt)
            mma16816(cb[mt][0], cb[mt][1], cb[mt][2], cb[mt][3],
                     EA[mt][2][0], EA[mt][2][1], EA[mt][2][2], EA[mt][2][3],
                     b0[2], b1[2]);
        #pragma unroll
        for (int mt = 0; mt < 4; ++mt)
            mma16816(ca[mt][0], ca[mt][1], ca[mt][2], ca[mt][3],
                     EA[mt][1][0], EA[mt][1][1], EA[mt][1][2], EA[mt][1][3],
                     b0[1], b1[1]);
        #pragma unroll
        for (int mt = 0; mt < 4; ++mt)
            mma16816(cb[mt][0], cb[mt][1], cb[mt][2], cb[mt][3],
                     EA[mt][3][0], EA[mt][3][1], EA[mt][3][2], EA[mt][3][3],
                     b0[3], b1[3]);

        // select mt = tig (this lane's owned tile), then combine the two halves
        float A1 = ca[0][0], B1 = cb[0][0], A2 = ca[0][2], B2 = cb[0][2];
        if (tig == 1) { A1 = ca[1][0]; B1 = cb[1][0]; A2 = ca[1][2]; B2 = cb[1][2]; }
        if (tig == 2) { A1 = ca[2][0]; B1 = cb[2][0]; A2 = ca[2][2]; B2 = cb[2][2]; }
        if (tig == 3) { A1 = ca[3][0]; B1 = cb[3][0]; A2 = ca[3][2]; B2 = cb[3][2]; }
        const float D1 = A1 + B1;
        const float D2 = A2 + B2;

        // ---- w_t = D * exp(logit_t) * rn   (fp32)
        w1 = D1 * F1 * rn;
        w2 = D2 * F2 * rn;

        // ---- off-chain bookkeeping (stable lag-1 normalizer on actual w_t[0])
        cacc += lnApp;                              // account rn applied this step
        float vb = __shfl_sync(FULL, w1, 0);        // w_t[0] lives on lane 0
        vb = fminf(fmaxf(vb, 1e-30f), 1e30f);
        rn = frcp(vb);
        lnApp = -__logf(rn);

        F1 = FnA; F2 = FnB;
        L1A = L2A; L1B = L2B;
        L2A = LnA; L2B = LnB;
    }

    // ---- logZ = C + ln( sum_j w_{L-1}[j] )
    float s = w1 + w2;
    #pragma unroll
    for (int o = 16; o; o >>= 1) s += __shfl_xor_sync(FULL, s, o);
    const float logZ = cacc + __logf(s);

    // ---- gold path score (lane-parallel over t; order-free sum)
    const int* tg = tags + (size_t)g * TT;
    const int tg0 = __ldg(tg);
    const float first = __ldg(init + tg0) + __ldg(lg + tg0);
    float gs = 0.0f;
    for (int t = 1 + lane; t < len; t += 32) {
        const int tc = __ldg(tg + t);
        const int tp = __ldg(tg + t - 1);
        gs += __ldg(trans + tc * CC + tp) + __ldg(lg + t * CC + tc);
    }
    #pragma unroll
    for (int o = 16; o; o >>= 1) gs += __shfl_xor_sync(FULL, gs, o);

    if (lane == 0) out[g] = logZ - (first + gs);
}

extern "C" void kernel_launch(void* const* d_in, const int* in_sizes, int n_in,
                              void* d_out, int out_size)
{
    const float* logits = (const float*)d_in[0];
    const float* trans  = (const float*)d_in[1];
    const float* init   = (const float*)d_in[2];
    const int*   lens   = (const int*)  d_in[3];
    const int*   tags   = (const int*)  d_in[4];
    float*       out    = (float*)d_out;

    crf_fwd_kernel<<<NB / 4, 128>>>(logits, trans, init, lens, tags, out);
}

// round 11
// speedup vs baseline: 1.5575x; 1.5575x over previous
#include <cuda_runtime.h>

#define NB 512
#define TT 1024
#define CC 64

typedef unsigned int u32;
typedef unsigned short u16;

__device__ __forceinline__ u32 pkbf2(float lo, float hi) {
    // d[31:16] = bf16(hi), d[15:0] = bf16(lo)
    u32 r; asm("cvt.rn.bf16x2.f32 %0, %1, %2;" : "=r"(r) : "f"(hi), "f"(lo)); return r;
}
__device__ __forceinline__ u16 f2bf(float x) {
    u16 r; asm("cvt.rn.bf16.f32 %0, %1;" : "=h"(r) : "f"(x)); return r;
}
__device__ __forceinline__ float frcp(float x) {
    float r; asm("rcp.approx.f32 %0, %1;" : "=f"(r) : "f"(x)); return r;
}
__device__ __forceinline__ void mma16816(float& c0, float& c1, float& c2, float& c3,
                                         u32 a0, u32 a1, u32 a2, u32 a3,
                                         u32 b0, u32 b1) {
    asm("mma.sync.aligned.m16n8k16.row.col.f32.bf16.bf16.f32 "
        "{%0,%1,%2,%3}, {%4,%5,%6,%7}, {%8,%9}, {%0,%1,%2,%3};"
        : "+f"(c0), "+f"(c1), "+f"(c2), "+f"(c3)
        : "r"(a0), "r"(a1), "r"(a2), "r"(a3), "r"(b0), "r"(b1));
}

__global__ void __launch_bounds__(128, 1) crf_fwd_kernel(
    const float* __restrict__ logits,   // [NB, TT, CC]
    const float* __restrict__ trans,    // [CC, CC]  trans[i][j] = score j->i
    const float* __restrict__ init,     // [CC]
    const int*   __restrict__ lengths,  // [NB]
    const int*   __restrict__ tags,     // [NB, TT]
    float*       __restrict__ out)      // [NB]
{
    // per-warp w vector in bf16, double-buffered (64 bf16 = 128 B per buffer)
    __shared__ __align__(16) u16 wsh[4][2][CC];

    const int wid  = threadIdx.x >> 5;
    const int lane = threadIdx.x & 31;
    const int g    = blockIdx.x * 4 + wid;          // grid=128 -> g in [0,512)

    const float* lg = logits + (size_t)g * TT * CC;
    const int len = lengths[g];                     // in [2, 1024], uniform per warp

    const int gid = lane >> 2;                      // 0..7
    const int tig = lane & 3;                       // 0..3
    const int r1  = gid + 16 * tig;                 // this lane's owned states
    const int r2  = r1 + 8;                         // (lane 0 -> rows 0, 8)

    // ---- preload E = exp(trans) as bf16 A-fragments: EA[mt][kt][4]
    u32 EA[4][4][4];
    #pragma unroll
    for (int mt = 0; mt < 4; ++mt) {
        const int row = 16 * mt + gid;
        #pragma unroll
        for (int kt = 0; kt < 4; ++kt) {
            const int col = 16 * kt + 2 * tig;
            const float e00 = __expf(__ldg(trans + row * CC + col));
            const float e01 = __expf(__ldg(trans + row * CC + col + 1));
            const float e10 = __expf(__ldg(trans + (row + 8) * CC + col));
            const float e11 = __expf(__ldg(trans + (row + 8) * CC + col + 1));
            const float e08 = __expf(__ldg(trans + row * CC + col + 8));
            const float e09 = __expf(__ldg(trans + row * CC + col + 9));
            const float e18 = __expf(__ldg(trans + (row + 8) * CC + col + 8));
            const float e19 = __expf(__ldg(trans + (row + 8) * CC + col + 9));
            EA[mt][kt][0] = pkbf2(e00, e01);   // rows gid,   cols 2tig..+1
            EA[mt][kt][1] = pkbf2(e10, e11);   // rows gid+8, cols 2tig..+1
            EA[mt][kt][2] = pkbf2(e08, e09);   // rows gid,   cols 2tig+8..+9
            EA[mt][kt][3] = pkbf2(e18, e19);   // rows gid+8, cols 2tig+8..+9
        }
    }

    // ---- w_0 = exp(init + logits[0])
    float w1 = __expf(__ldg(init + r1) + __ldg(lg + r1));
    float w2 = __expf(__ldg(init + r2) + __ldg(lg + r2));
    wsh[wid][0][r1] = f2bf(w1);
    wsh[wid][0][r2] = f2bf(w2);
    __syncwarp();

    // ---- logit pipeline: F for t=1; raw logits for t+1, t+2 (distance-3 LDG cover)
    float F1 = __expf(__ldg(lg + CC + r1));
    float F2 = __expf(__ldg(lg + CC + r2));
    const int c2i = (2 < len) ? 2 : (len - 1);
    const int c3i = (3 < len) ? 3 : (len - 1);
    float L1A = __ldg(lg + c2i * CC + r1), L1B = __ldg(lg + c2i * CC + r2);
    float L2A = __ldg(lg + c3i * CC + r1), L2B = __ldg(lg + c3i * CC + r2);

    float rn = 1.0f;      // normalizer applied this step (lag-1)
    float lnApp = 0.0f;   // -ln(rn)
    float cacc = 0.0f;    // running log-shift
    int buf = 0;

    const u32 FULL = 0xffffffffu;

    for (int t = 1; t < len; ++t) {
        // LDG for logits[t+3] first — ~2 steps of latency cover
        const int tn = (t + 3 < len) ? (t + 3) : (len - 1);
        const float LnA = __ldg(lg + tn * CC + r1);
        const float LnB = __ldg(lg + tn * CC + r2);
        // F for t+1 (MUFU off the critical chain)
        const float FnA = __expf(L1A);
        const float FnB = __expf(L1B);

        // ---- B fragments: B[k][n] = w[k] for all n (broadcast LDS.b32 pairs)
        const u32* wp = (const u32*)(&wsh[wid][buf][0]);
        u32 b0[4], b1[4];
        #pragma unroll
        for (int kt = 0; kt < 4; ++kt) {
            b0[kt] = wp[8 * kt + tig];        // k = 16kt+2tig, +1
            b1[kt] = wp[8 * kt + tig + 4];    // k = 16kt+2tig+8, +9
        }

        // ---- D = E * w via 16 HMMA; depth-2 accumulation (8 independent chains)
        float ca[4][4], cb[4][4];
        #pragma unroll
        for (int mt = 0; mt < 4; ++mt)
            #pragma unroll
            for (int i = 0; i < 4; ++i) { ca[mt][i] = 0.0f; cb[mt][i] = 0.0f; }
        #pragma unroll
        for (int mt = 0; mt < 4; ++mt)
            mma16816(ca[mt][0], ca[mt][1], ca[mt][2], ca[mt][3],
                     EA[mt][0][0], EA[mt][0][1], EA[mt][0][2], EA[mt][0][3],
                     b0[0], b1[0]);
        #pragma unroll
        for (int mt = 0; mt < 4; ++mt)
            mma16816(cb[mt][0], cb[mt][1], cb[mt][2], cb[mt][3],
                     EA[mt][2][0], EA[mt][2][1], EA[mt][2][2], EA[mt][2][3],
                     b0[2], b1[2]);
        #pragma unroll
        for (int mt = 0; mt < 4; ++mt)
            mma16816(ca[mt][0], ca[mt][1], ca[mt][2], ca[mt][3],
                     EA[mt][1][0], EA[mt][1][1], EA[mt][1][2], EA[mt][1][3],
                     b0[1], b1[1]);
        #pragma unroll
        for (int mt = 0; mt < 4; ++mt)
            mma16816(cb[mt][0], cb[mt][1], cb[mt][2], cb[mt][3],
                     EA[mt][3][0], EA[mt][3][1], EA[mt][3][2], EA[mt][3][3],
                     b0[3], b1[3]);

        // select mt = tig (this lane's owned tile), then combine the two halves
        float A1 = ca[0][0], B1 = cb[0][0], A2 = ca[0][2], B2 = cb[0][2];
        if (tig == 1) { A1 = ca[1][0]; B1 = cb[1][0]; A2 = ca[1][2]; B2 = cb[1][2]; }
        if (tig == 2) { A1 = ca[2][0]; B1 = cb[2][0]; A2 = ca[2][2]; B2 = cb[2][2]; }
        if (tig == 3) { A1 = ca[3][0]; B1 = cb[3][0]; A2 = ca[3][2]; B2 = cb[3][2]; }
        const float D1 = A1 + B1;
        const float D2 = A2 + B2;

        // ---- early normalizer broadcast: overlap SHFL with epilogue + STS
        const float df = D1 * F1;                    // lane0's df = D[0]*F[0]
        const float df0 = __shfl_sync(FULL, df, 0);  // issues now, lands during STS

        // ---- w_t = D * exp(logit_t) * rn   (fp32)
        w1 = df * rn;
        w2 = D2 * F2 * rn;
        wsh[wid][buf ^ 1][r1] = f2bf(w1);
        wsh[wid][buf ^ 1][r2] = f2bf(w2);
        __syncwarp();
        buf ^= 1;

        // ---- off-chain bookkeeping (stable lag-1 normalizer on actual w_t[0])
        cacc += lnApp;                               // account rn applied this step
        float vb = df0 * rn;                         // == w_t[0]
        vb = fminf(fmaxf(vb, 1e-30f), 1e30f);
        rn = frcp(vb);
        lnApp = -__logf(rn);

        F1 = FnA; F2 = FnB;
        L1A = L2A; L1B = L2B;
        L2A = LnA; L2B = LnB;
    }

    // ---- logZ = C + ln( sum_j w_{L-1}[j] )
    float s = w1 + w2;
    #pragma unroll
    for (int o = 16; o; o >>= 1) s += __shfl_xor_sync(FULL, s, o);
    const float logZ = cacc + __logf(s);

    // ---- gold path score (lane-parallel over t; order-free sum)
    const int* tg = tags + (size_t)g * TT;
    const int tg0 = __ldg(tg);
    const float first = __ldg(init + tg0) + __ldg(lg + tg0);
    float gs = 0.0f;
    for (int t = 1 + lane; t < len; t += 32) {
        const int tc = __ldg(tg + t);
        const int tp = __ldg(tg + t - 1);
        gs += __ldg(trans + tc * CC + tp) + __ldg(lg + t * CC + tc);
    }
    #pragma unroll
    for (int o = 16; o; o >>= 1) gs += __shfl_xor_sync(FULL, gs, o);

    if (lane == 0) out[g] = logZ - (first + gs);
}

extern "C" void kernel_launch(void* const* d_in, const int* in_sizes, int n_in,
                              void* d_out, int out_size)
{
    const float* logits = (const float*)d_in[0];
    const float* trans  = (const float*)d_in[1];
    const float* init   = (const float*)d_in[2];
    const int*   lens   = (const int*)  d_in[3];
    const int*   tags   = (const int*)  d_in[4];
    float*       out    = (float*)d_out;

    crf_fwd_kernel<<<NB / 4, 128>>>(logits, trans, init, lens, tags, out);
}